// round 3
// baseline (speedup 1.0000x reference)
#include <cuda_runtime.h>

#define N_NODES 100000
#define N_EDGES 1000000
#define N_GRAPHS 64
#define HD 64
#define EPSV 1e-5f

// ---------------- scratch (device globals; no allocation allowed) ------------
__device__ float g_y [N_NODES * HD];   // GEMM output per layer
__device__ float g_xa[N_NODES * HD];   // ping
__device__ float g_xb[N_NODES * HD];   // pong
__device__ int   g_deg[N_NODES];
__device__ float g_dinv[N_NODES];
__device__ int   g_rowptr[N_NODES + 1];
__device__ int   g_cursor[N_NODES];
__device__ int2  g_csr[N_EDGES];       // .x = src node, .y = bits of dinv[src]
__device__ int   g_partial[256];
__device__ float g_ssum[N_GRAPHS * HD];
__device__ float g_cnt[N_GRAPHS];

// ---------------- degree / normalization ------------------------------------
__global__ void k_init_deg() {
    int i = blockIdx.x * blockDim.x + threadIdx.x;
    if (i < N_NODES) g_deg[i] = 1;           // self loop
}

__global__ void k_count(const int* __restrict__ dst) {
    int e = blockIdx.x * blockDim.x + threadIdx.x;
    if (e < N_EDGES) atomicAdd(&g_deg[dst[e]], 1);
}

__global__ void k_dinv() {
    int i = blockIdx.x * blockDim.x + threadIdx.x;
    if (i < N_NODES) g_dinv[i] = rsqrtf((float)g_deg[i]);
}

// ---------------- exclusive scan of (deg-1) -> rowptr ------------------------
__global__ void k_scan_a() {
    __shared__ int sh[512];
    int tid = threadIdx.x;
    int i = blockIdx.x * 512 + tid;
    sh[tid] = (i < N_NODES) ? (g_deg[i] - 1) : 0;
    __syncthreads();
    for (int off = 256; off > 0; off >>= 1) {
        if (tid < off) sh[tid] += sh[tid + off];
        __syncthreads();
    }
    if (tid == 0) g_partial[blockIdx.x] = sh[0];
}

__global__ void k_scan_b(int nblk) {
    // single thread: 196 values, trivial
    int s = 0;
    for (int b = 0; b < nblk; b++) { int t = g_partial[b]; g_partial[b] = s; s += t; }
    g_rowptr[N_NODES] = N_EDGES;
}

__global__ void k_scan_c() {
    __shared__ int sh[512];
    int tid = threadIdx.x;
    int i = blockIdx.x * 512 + tid;
    int v = (i < N_NODES) ? (g_deg[i] - 1) : 0;
    sh[tid] = v;
    __syncthreads();
    // inclusive Hillis-Steele
    for (int off = 1; off < 512; off <<= 1) {
        int t = (tid >= off) ? sh[tid - off] : 0;
        __syncthreads();
        sh[tid] += t;
        __syncthreads();
    }
    if (i < N_NODES) {
        int ex = g_partial[blockIdx.x] + sh[tid] - v;
        g_rowptr[i] = ex;
        g_cursor[i] = ex;
    }
}

__global__ void k_scatter(const int* __restrict__ src, const int* __restrict__ dst) {
    int e = blockIdx.x * blockDim.x + threadIdx.x;
    if (e >= N_EDGES) return;
    int d = dst[e];
    int s = src[e];
    int p = atomicAdd(&g_cursor[d], 1);
    g_csr[p] = make_int2(s, __float_as_int(g_dinv[s]));
}

// ---------------- GEMM: Y = X @ W (N x 64 @ 64 x 64), W column in registers --
__global__ void __launch_bounds__(256) k_gemm(const float* __restrict__ Xext, int xsel,
                                              const float* __restrict__ W) {
    __shared__ float xs[64 * 64];
    const float* X = (xsel < 0) ? Xext : (xsel == 0 ? (const float*)g_xa : (const float*)g_xb);

    int tid  = threadIdx.x;
    int c    = tid & 63;        // output column
    int rsub = tid >> 6;        // 0..3

    float w[64];
#pragma unroll
    for (int j = 0; j < 64; j++) w[j] = W[j * 64 + c];

    int rt = blockIdx.x * 64;
#pragma unroll
    for (int it = 0; it < 16; it++) {
        int idx = it * 256 + tid;
        int r = idx >> 6, cc = idx & 63;
        int row = rt + r;
        xs[idx] = (row < N_NODES) ? X[row * 64 + cc] : 0.f;
    }
    __syncthreads();

#pragma unroll
    for (int k = 0; k < 16; k++) {
        int r = (rsub << 4) + k;
        const float4* xv = (const float4*)&xs[r * 64];
        float acc = 0.f;
#pragma unroll
        for (int j = 0; j < 16; j++) {
            float4 x4 = xv[j];
            acc += x4.x * w[4 * j] + x4.y * w[4 * j + 1] + x4.z * w[4 * j + 2] + x4.w * w[4 * j + 3];
        }
        int row = rt + r;
        if (row < N_NODES) g_y[row * 64 + c] = acc;
    }
}

// ---------------- fused aggregation + bias + ReLU + BN + residual ------------
// warp per node; lane handles dims {lane, lane+32}
__global__ void __launch_bounds__(256) k_agg(int res_sel, int out_sel,
                                             const float* __restrict__ bias,
                                             const float* __restrict__ gamma,
                                             const float* __restrict__ beta,
                                             const float* __restrict__ mean,
                                             const float* __restrict__ var) {
    int node = (blockIdx.x * blockDim.x + threadIdx.x) >> 5;
    int lane = threadIdx.x & 31;
    if (node >= N_NODES) return;

    const float* Y = g_y;
    float*       OUT = out_sel ? g_xb : g_xa;
    const float* RES = (res_sel < 0) ? nullptr : (res_sel == 0 ? (const float*)g_xa : (const float*)g_xb);

    int beg = g_rowptr[node], end = g_rowptr[node + 1];
    float acc0 = 0.f, acc1 = 0.f;
    int e = beg;
    for (; e + 1 < end; e += 2) {
        int2 c0 = g_csr[e];
        int2 c1 = g_csr[e + 1];
        float w0 = __int_as_float(c0.y);
        float w1 = __int_as_float(c1.y);
        const float* p0 = Y + (long)c0.x * 64;
        const float* p1 = Y + (long)c1.x * 64;
        float a00 = p0[lane],      a01 = p0[lane + 32];
        float a10 = p1[lane],      a11 = p1[lane + 32];
        acc0 += w0 * a00 + w1 * a10;
        acc1 += w0 * a01 + w1 * a11;
    }
    if (e < end) {
        int2 c0 = g_csr[e];
        float w0 = __int_as_float(c0.y);
        const float* p0 = Y + (long)c0.x * 64;
        acc0 += w0 * p0[lane];
        acc1 += w0 * p0[lane + 32];
    }

    float di = g_dinv[node];
    acc0 = di * (acc0 + di * Y[node * 64 + lane])      + bias[lane];
    acc1 = di * (acc1 + di * Y[node * 64 + lane + 32]) + bias[lane + 32];
    acc0 = fmaxf(acc0, 0.f);
    acc1 = fmaxf(acc1, 0.f);
    float s0 = gamma[lane]      * rsqrtf(var[lane]      + EPSV);
    float s1 = gamma[lane + 32] * rsqrtf(var[lane + 32] + EPSV);
    acc0 = (acc0 - mean[lane])      * s0 + beta[lane];
    acc1 = (acc1 - mean[lane + 32]) * s1 + beta[lane + 32];
    if (RES) {
        acc0 += RES[node * 64 + lane];
        acc1 += RES[node * 64 + lane + 32];
    }
    OUT[node * 64 + lane]      = acc0;
    OUT[node * 64 + lane + 32] = acc1;
}

// ---------------- pooling (batch is sorted -> run-length accumulate) ---------
__global__ void k_zero_pool() {
    int i = blockIdx.x * blockDim.x + threadIdx.x;
    if (i < N_GRAPHS * HD) g_ssum[i] = 0.f;
    if (i < N_GRAPHS)      g_cnt[i] = 0.f;
}

__global__ void k_pool(int xsel, const int* __restrict__ batch) {
    const float* X5 = xsel == 0 ? (const float*)g_xa : (const float*)g_xb;
    int c = threadIdx.x;                 // 0..63 channel
    int start = blockIdx.x * 512;
    if (start >= N_NODES) return;
    int endn = min(start + 512, N_NODES);
    float acc = 0.f;
    int run = 0;
    int gcur = batch[start];
    for (int n = start; n < endn; n++) {
        int g = batch[n];
        if (g != gcur) {
            atomicAdd(&g_ssum[gcur * 64 + c], acc);
            if (c == 0) atomicAdd(&g_cnt[gcur], (float)run);
            acc = 0.f; run = 0; gcur = g;
        }
        acc += X5[n * 64 + c];
        run++;
    }
    atomicAdd(&g_ssum[gcur * 64 + c], acc);
    if (c == 0) atomicAdd(&g_cnt[gcur], (float)run);
}

// ---------------- MLP head ---------------------------------------------------
__global__ void k_head(const float* __restrict__ hW1, const float* __restrict__ hb1,
                       const float* __restrict__ hg,  const float* __restrict__ hbeta,
                       const float* __restrict__ hm,  const float* __restrict__ hv,
                       const float* __restrict__ hW2, const float* __restrict__ hb2,
                       float* __restrict__ out) {
    int g = threadIdx.x;
    if (g >= N_GRAPHS) return;
    float inv = 1.f / fmaxf(g_cnt[g], 1.f);
    float gv[64];
#pragma unroll
    for (int k = 0; k < 64; k++) gv[k] = g_ssum[g * 64 + k] * inv;
    float o = hb2[0];
    for (int j = 0; j < 32; j++) {
        float s = hb1[j];
#pragma unroll
        for (int k = 0; k < 64; k++) s += gv[k] * hW1[k * 32 + j];
        s = fmaxf(s, 0.f);
        s = (s - hm[j]) * (hg[j] * rsqrtf(hv[j] + EPSV)) + hbeta[j];
        o += s * hW2[j];
    }
    out[g] = o;
}

// ---------------- launcher ---------------------------------------------------
extern "C" void kernel_launch(void* const* d_in, const int* in_sizes, int n_in,
                              void* d_out, int out_size) {
    const float* x     = (const float*)d_in[0];
    const int*   ei    = (const int*)  d_in[1];
    const int*   batch = (const int*)  d_in[2];
    const float* Wc    = (const float*)d_in[3];
    const float* bc    = (const float*)d_in[4];
    const float* bn_g  = (const float*)d_in[5];
    const float* bn_b  = (const float*)d_in[6];
    const float* bn_m  = (const float*)d_in[7];
    const float* bn_v  = (const float*)d_in[8];
    const float* hW1   = (const float*)d_in[9];
    const float* hb1   = (const float*)d_in[10];
    const float* hg    = (const float*)d_in[11];
    const float* hbe   = (const float*)d_in[12];
    const float* hm    = (const float*)d_in[13];
    const float* hv    = (const float*)d_in[14];
    const float* hW2   = (const float*)d_in[15];
    const float* hb2   = (const float*)d_in[16];
    float* out = (float*)d_out;

    const int* src = ei;
    const int* dst = ei + N_EDGES;

    // --- CSR build (once per call, reused by all 5 layers) ---
    k_init_deg<<<(N_NODES + 255) / 256, 256>>>();
    k_count  <<<(N_EDGES + 255) / 256, 256>>>(dst);
    k_dinv   <<<(N_NODES + 255) / 256, 256>>>();
    int nblk = (N_NODES + 511) / 512;       // 196
    k_scan_a <<<nblk, 512>>>();
    k_scan_b <<<1, 1>>>(nblk);
    k_scan_c <<<nblk, 512>>>();
    k_scatter<<<(N_EDGES + 255) / 256, 256>>>(src, dst);

    // --- 5 GCN layers ---
    const int gemm_grid = (N_NODES + 63) / 64;        // 1563
    const int agg_grid  = (N_NODES * 32 + 255) / 256; // 12500

    // layer 0: in = x (external), out = xa, no residual
    k_gemm<<<gemm_grid, 256>>>(x, -1, Wc + 0 * 4096);
    k_agg <<<agg_grid, 256>>>(-1, 0, bc + 0, bn_g + 0, bn_b + 0, bn_m + 0, bn_v + 0);
    // layer 1: in = xa, res = xa, out = xb
    k_gemm<<<gemm_grid, 256>>>(nullptr, 0, Wc + 1 * 4096);
    k_agg <<<agg_grid, 256>>>(0, 1, bc + 64, bn_g + 64, bn_b + 64, bn_m + 64, bn_v + 64);
    // layer 2: in = xb, res = xb, out = xa
    k_gemm<<<gemm_grid, 256>>>(nullptr, 1, Wc + 2 * 4096);
    k_agg <<<agg_grid, 256>>>(1, 0, bc + 128, bn_g + 128, bn_b + 128, bn_m + 128, bn_v + 128);
    // layer 3: in = xa, res = xa, out = xb
    k_gemm<<<gemm_grid, 256>>>(nullptr, 0, Wc + 3 * 4096);
    k_agg <<<agg_grid, 256>>>(0, 1, bc + 192, bn_g + 192, bn_b + 192, bn_m + 192, bn_v + 192);
    // layer 4: in = xb, res = xb, out = xa  (x5 lives in xa)
    k_gemm<<<gemm_grid, 256>>>(nullptr, 1, Wc + 4 * 4096);
    k_agg <<<agg_grid, 256>>>(1, 0, bc + 256, bn_g + 256, bn_b + 256, bn_m + 256, bn_v + 256);

    // --- pool + head ---
    k_zero_pool<<<(N_GRAPHS * HD + 255) / 256, 256>>>();
    k_pool<<<(N_NODES + 511) / 512, 64>>>(0, batch);
    k_head<<<1, 64>>>(hW1, hb1, hg, hbe, hm, hv, hW2, hb2, out);
}

// round 4
// speedup vs baseline: 1.0398x; 1.0398x over previous
#include <cuda_runtime.h>

#define N_NODES 100000
#define N_EDGES 1000000
#define N_GRAPHS 64
#define HD 64
#define EPSV 1e-5f

// ---------------- scratch (device globals; no allocation allowed) ------------
__device__ float g_y [N_NODES * HD];   // GEMM output per layer
__device__ float g_xa[N_NODES * HD];   // ping
__device__ float g_xb[N_NODES * HD];   // pong
__device__ int   g_deg[N_NODES];
__device__ float g_dinv[N_NODES];
__device__ int   g_rowptr[N_NODES + 1];
__device__ int   g_cursor[N_NODES];
__device__ int2  g_csr[N_EDGES];       // .x = src node, .y = bits of dinv[src]
__device__ int   g_partial[256];
__device__ float g_ssum[N_GRAPHS * HD];
__device__ float g_cnt[N_GRAPHS];

// ---------------- degree / normalization ------------------------------------
__global__ void k_init_deg() {
    int i = blockIdx.x * blockDim.x + threadIdx.x;
    if (i < N_NODES) g_deg[i] = 1;           // self loop
}

__global__ void k_count(const int* __restrict__ dst) {
    int e = blockIdx.x * blockDim.x + threadIdx.x;
    if (e < N_EDGES) atomicAdd(&g_deg[dst[e]], 1);
}

__global__ void k_dinv() {
    int i = blockIdx.x * blockDim.x + threadIdx.x;
    if (i < N_NODES) g_dinv[i] = rsqrtf((float)g_deg[i]);
}

// ---------------- exclusive scan of (deg-1) -> rowptr ------------------------
__global__ void k_scan_a() {
    __shared__ int sh[512];
    int tid = threadIdx.x;
    int i = blockIdx.x * 512 + tid;
    sh[tid] = (i < N_NODES) ? (g_deg[i] - 1) : 0;
    __syncthreads();
    for (int off = 256; off > 0; off >>= 1) {
        if (tid < off) sh[tid] += sh[tid + off];
        __syncthreads();
    }
    if (tid == 0) g_partial[blockIdx.x] = sh[0];
}

__global__ void k_scan_b(int nblk) {
    int s = 0;
    for (int b = 0; b < nblk; b++) { int t = g_partial[b]; g_partial[b] = s; s += t; }
    g_rowptr[N_NODES] = N_EDGES;
}

__global__ void k_scan_c() {
    __shared__ int sh[512];
    int tid = threadIdx.x;
    int i = blockIdx.x * 512 + tid;
    int v = (i < N_NODES) ? (g_deg[i] - 1) : 0;
    sh[tid] = v;
    __syncthreads();
    for (int off = 1; off < 512; off <<= 1) {
        int t = (tid >= off) ? sh[tid - off] : 0;
        __syncthreads();
        sh[tid] += t;
        __syncthreads();
    }
    if (i < N_NODES) {
        int ex = g_partial[blockIdx.x] + sh[tid] - v;
        g_rowptr[i] = ex;
        g_cursor[i] = ex;
    }
}

__global__ void k_scatter(const int* __restrict__ src, const int* __restrict__ dst) {
    int e = blockIdx.x * blockDim.x + threadIdx.x;
    if (e >= N_EDGES) return;
    int d = dst[e];
    int s = src[e];
    int p = atomicAdd(&g_cursor[d], 1);
    g_csr[p] = make_int2(s, __float_as_int(g_dinv[s]));
}

// ---------------- GEMM: Y = X @ W via packed fma.rn.f32x2 --------------------
// 128 rows/block, 256 threads. x tile stored K-major in smem (row-pairs
// contiguous) with XOR swizzle so the transpose store is bank-conflict-free.
// Thread = one output column c, 32 rows (16 row-pairs), FFMA2 over pairs.
__global__ void __launch_bounds__(256) k_gemm(const float* __restrict__ Xext, int xsel,
                                              const float* __restrict__ W) {
    __shared__ float xs[64 * 128];   // xs[k][...] : 128 floats per k (swizzled pairs)
    const float* X = (xsel < 0) ? Xext : (xsel == 0 ? (const float*)g_xa : (const float*)g_xb);

    int tid  = threadIdx.x;
    int c    = tid & 63;     // output column
    int rsub = tid >> 6;     // 0..3 -> rows rsub*32 .. rsub*32+31

    // W column c into registers
    float w[64];
#pragma unroll
    for (int k = 0; k < 64; k++) w[k] = W[k * 64 + c];

    int rt = blockIdx.x * 128;

    // load + transpose + swizzle-store: idx -> (cq = idx&15, row = idx>>4)
    // half-warp shares a row -> gmem float4 reads coalesced (256B/half-warp);
    // store banks: 2*((row>>1) ^ g(K)) + (row&1) -> 32 distinct banks per warp.
#pragma unroll
    for (int it = 0; it < 8; it++) {
        int idx = it * 256 + tid;        // 0..2047
        int cq  = idx & 15;
        int row = idx >> 4;              // 0..127
        int grow = rt + row;
        float4 x4 = make_float4(0.f, 0.f, 0.f, 0.f);
        if (grow < N_NODES) x4 = *(const float4*)&X[grow * 64 + 4 * cq];
        int u  = row >> 1;
        int rb = row & 1;
        float vals[4] = {x4.x, x4.y, x4.z, x4.w};
#pragma unroll
        for (int m = 0; m < 4; m++) {
            int K  = 4 * cq + m;
            int gk = (K + (K >> 2)) & 15;
            xs[K * 128 + 2 * (u ^ gk) + rb] = vals[m];
        }
    }
    __syncthreads();

    unsigned long long acc[16];
#pragma unroll
    for (int j = 0; j < 16; j++) acc[j] = 0ULL;

#pragma unroll
    for (int k = 0; k < 64; k++) {
        const int g = (k + (k >> 2)) & 15;
        unsigned long long wp;
        asm("mov.b64 %0, {%1, %1};" : "=l"(wp) : "f"(w[k]));
        const float* base = &xs[k * 128 + rsub * 32];
#pragma unroll
        for (int j = 0; j < 16; j++) {
            float2 x2 = *(const float2*)&base[2 * (j ^ g)];   // broadcast LDS.64
            unsigned long long xv;
            asm("mov.b64 %0, {%1, %2};" : "=l"(xv) : "f"(x2.x), "f"(x2.y));
            asm("fma.rn.f32x2 %0, %1, %2, %0;" : "+l"(acc[j]) : "l"(xv), "l"(wp));
        }
    }

#pragma unroll
    for (int j = 0; j < 16; j++) {
        int row = rt + rsub * 32 + 2 * j;
        float lo, hi;
        asm("mov.b64 {%0, %1}, %2;" : "=f"(lo), "=f"(hi) : "l"(acc[j]));
        if (row < N_NODES)     g_y[row * 64 + c]       = lo;
        if (row + 1 < N_NODES) g_y[(row + 1) * 64 + c] = hi;
    }
}

// ---------------- fused aggregation + bias + ReLU + BN + residual ------------
// 2 nodes per warp (one per half-warp); lane handles 4 dims via float4.
// Per edge: one LDG.128 half-warp gather (256B) of the source row.
__global__ void __launch_bounds__(256) k_agg(int res_sel, int out_sel,
                                             const float* __restrict__ bias,
                                             const float* __restrict__ gamma,
                                             const float* __restrict__ beta,
                                             const float* __restrict__ mean,
                                             const float* __restrict__ var) {
    int gw   = (blockIdx.x * blockDim.x + threadIdx.x) >> 5;  // global warp
    int lane = threadIdx.x & 31;
    int node = gw * 2 + (lane >> 4);
    if (node >= N_NODES) return;
    int q = lane & 15;                                        // float4 slot 0..15

    const float*  Y   = g_y;
    float*        OUT = out_sel ? g_xb : g_xa;
    const float*  RES = (res_sel < 0) ? nullptr
                                      : (res_sel == 0 ? (const float*)g_xa : (const float*)g_xb);

    int beg = g_rowptr[node], end = g_rowptr[node + 1];
    float4 a = make_float4(0.f, 0.f, 0.f, 0.f);

    int e = beg;
    for (; e + 1 < end; e += 2) {
        int2 c0 = g_csr[e];
        int2 c1 = g_csr[e + 1];
        float4 v0 = ((const float4*)(Y + (size_t)c0.x * 64))[q];
        float4 v1 = ((const float4*)(Y + (size_t)c1.x * 64))[q];
        float w0 = __int_as_float(c0.y);
        float w1 = __int_as_float(c1.y);
        a.x += w0 * v0.x + w1 * v1.x;
        a.y += w0 * v0.y + w1 * v1.y;
        a.z += w0 * v0.z + w1 * v1.z;
        a.w += w0 * v0.w + w1 * v1.w;
    }
    if (e < end) {
        int2 c0 = g_csr[e];
        float4 v0 = ((const float4*)(Y + (size_t)c0.x * 64))[q];
        float w0 = __int_as_float(c0.y);
        a.x += w0 * v0.x;  a.y += w0 * v0.y;
        a.z += w0 * v0.z;  a.w += w0 * v0.w;
    }

    float  di   = g_dinv[node];
    float4 self = ((const float4*)(Y + (size_t)node * 64))[q];
    float4 b  = ((const float4*)bias)[q];
    a.x = di * (a.x + di * self.x) + b.x;
    a.y = di * (a.y + di * self.y) + b.y;
    a.z = di * (a.z + di * self.z) + b.z;
    a.w = di * (a.w + di * self.w) + b.w;
    a.x = fmaxf(a.x, 0.f); a.y = fmaxf(a.y, 0.f);
    a.z = fmaxf(a.z, 0.f); a.w = fmaxf(a.w, 0.f);

    float4 ga = ((const float4*)gamma)[q];
    float4 be = ((const float4*)beta)[q];
    float4 mm = ((const float4*)mean)[q];
    float4 vv = ((const float4*)var)[q];
    float4 sc;
    sc.x = ga.x * rsqrtf(vv.x + EPSV);
    sc.y = ga.y * rsqrtf(vv.y + EPSV);
    sc.z = ga.z * rsqrtf(vv.z + EPSV);
    sc.w = ga.w * rsqrtf(vv.w + EPSV);
    a.x = (a.x - mm.x) * sc.x + be.x;
    a.y = (a.y - mm.y) * sc.y + be.y;
    a.z = (a.z - mm.z) * sc.z + be.z;
    a.w = (a.w - mm.w) * sc.w + be.w;

    if (RES) {
        float4 r = ((const float4*)(RES + (size_t)node * 64))[q];
        a.x += r.x; a.y += r.y; a.z += r.z; a.w += r.w;
    }
    ((float4*)(OUT + (size_t)node * 64))[q] = a;
}

// ---------------- pooling (batch is sorted -> run-length accumulate) ---------
__global__ void k_zero_pool() {
    int i = blockIdx.x * blockDim.x + threadIdx.x;
    if (i < N_GRAPHS * HD) g_ssum[i] = 0.f;
    if (i < N_GRAPHS)      g_cnt[i] = 0.f;
}

__global__ void k_pool(int xsel, const int* __restrict__ batch) {
    const float* X5 = xsel == 0 ? (const float*)g_xa : (const float*)g_xb;
    int c = threadIdx.x;                 // 0..63 channel
    int start = blockIdx.x * 512;
    if (start >= N_NODES) return;
    int endn = min(start + 512, N_NODES);
    float acc = 0.f;
    int run = 0;
    int gcur = batch[start];
    for (int n = start; n < endn; n++) {
        int g = batch[n];
        if (g != gcur) {
            atomicAdd(&g_ssum[gcur * 64 + c], acc);
            if (c == 0) atomicAdd(&g_cnt[gcur], (float)run);
            acc = 0.f; run = 0; gcur = g;
        }
        acc += X5[n * 64 + c];
        run++;
    }
    atomicAdd(&g_ssum[gcur * 64 + c], acc);
    if (c == 0) atomicAdd(&g_cnt[gcur], (float)run);
}

// ---------------- MLP head ---------------------------------------------------
__global__ void k_head(const float* __restrict__ hW1, const float* __restrict__ hb1,
                       const float* __restrict__ hg,  const float* __restrict__ hbeta,
                       const float* __restrict__ hm,  const float* __restrict__ hv,
                       const float* __restrict__ hW2, const float* __restrict__ hb2,
                       float* __restrict__ out) {
    int g = threadIdx.x;
    if (g >= N_GRAPHS) return;
    float inv = 1.f / fmaxf(g_cnt[g], 1.f);
    float gv[64];
#pragma unroll
    for (int k = 0; k < 64; k++) gv[k] = g_ssum[g * 64 + k] * inv;
    float o = hb2[0];
    for (int j = 0; j < 32; j++) {
        float s = hb1[j];
#pragma unroll
        for (int k = 0; k < 64; k++) s += gv[k] * hW1[k * 32 + j];
        s = fmaxf(s, 0.f);
        s = (s - hm[j]) * (hg[j] * rsqrtf(hv[j] + EPSV)) + hbeta[j];
        o += s * hW2[j];
    }
    out[g] = o;
}

// ---------------- launcher ---------------------------------------------------
extern "C" void kernel_launch(void* const* d_in, const int* in_sizes, int n_in,
                              void* d_out, int out_size) {
    const float* x     = (const float*)d_in[0];
    const int*   ei    = (const int*)  d_in[1];
    const int*   batch = (const int*)  d_in[2];
    const float* Wc    = (const float*)d_in[3];
    const float* bc    = (const float*)d_in[4];
    const float* bn_g  = (const float*)d_in[5];
    const float* bn_b  = (const float*)d_in[6];
    const float* bn_m  = (const float*)d_in[7];
    const float* bn_v  = (const float*)d_in[8];
    const float* hW1   = (const float*)d_in[9];
    const float* hb1   = (const float*)d_in[10];
    const float* hg    = (const float*)d_in[11];
    const float* hbe   = (const float*)d_in[12];
    const float* hm    = (const float*)d_in[13];
    const float* hv    = (const float*)d_in[14];
    const float* hW2   = (const float*)d_in[15];
    const float* hb2   = (const float*)d_in[16];
    float* out = (float*)d_out;

    const int* src = ei;
    const int* dst = ei + N_EDGES;

    // --- CSR build (reused by all 5 layers) ---
    k_zero_pool<<<(N_GRAPHS * HD + 255) / 256, 256>>>();
    k_init_deg<<<(N_NODES + 255) / 256, 256>>>();
    k_count  <<<(N_EDGES + 255) / 256, 256>>>(dst);
    k_dinv   <<<(N_NODES + 255) / 256, 256>>>();
    int nblk = (N_NODES + 511) / 512;       // 196
    k_scan_a <<<nblk, 512>>>();
    k_scan_b <<<1, 1>>>(nblk);
    k_scan_c <<<nblk, 512>>>();
    k_scatter<<<(N_EDGES + 255) / 256, 256>>>(src, dst);

    // --- 5 GCN layers ---
    const int gemm_grid = (N_NODES + 127) / 128;              // 782
    const int agg_grid  = ((N_NODES + 1) / 2 * 32 + 255) / 256; // 2 nodes/warp

    k_gemm<<<gemm_grid, 256>>>(x, -1, Wc + 0 * 4096);
    k_agg <<<agg_grid, 256>>>(-1, 0, bc + 0, bn_g + 0, bn_b + 0, bn_m + 0, bn_v + 0);
    k_gemm<<<gemm_grid, 256>>>(nullptr, 0, Wc + 1 * 4096);
    k_agg <<<agg_grid, 256>>>(0, 1, bc + 64, bn_g + 64, bn_b + 64, bn_m + 64, bn_v + 64);
    k_gemm<<<gemm_grid, 256>>>(nullptr, 1, Wc + 2 * 4096);
    k_agg <<<agg_grid, 256>>>(1, 0, bc + 128, bn_g + 128, bn_b + 128, bn_m + 128, bn_v + 128);
    k_gemm<<<gemm_grid, 256>>>(nullptr, 0, Wc + 3 * 4096);
    k_agg <<<agg_grid, 256>>>(0, 1, bc + 192, bn_g + 192, bn_b + 192, bn_m + 192, bn_v + 192);
    k_gemm<<<gemm_grid, 256>>>(nullptr, 1, Wc + 4 * 4096);
    k_agg <<<agg_grid, 256>>>(1, 0, bc + 256, bn_g + 256, bn_b + 256, bn_m + 256, bn_v + 256);

    // --- pool + head ---
    k_pool<<<(N_NODES + 511) / 512, 64>>>(0, batch);
    k_head<<<1, 64>>>(hW1, hb1, hg, hbe, hm, hv, hW2, hb2, out);
}

// round 5
// speedup vs baseline: 1.1952x; 1.1495x over previous
#include <cuda_runtime.h>
#include <cuda_fp16.h>

#define N_NODES 100000
#define N_EDGES 1000000
#define N_GRAPHS 64
#define HD 64
#define EPSV 1e-5f

// ---------------- scratch (device globals; no allocation allowed) ------------
__device__ __half g_yh[N_NODES * HD];  // GEMM output per layer (fp16, gathered)
__device__ float g_xa[N_NODES * HD];   // ping (layer outputs, fp32)
__device__ float g_xb[N_NODES * HD];   // pong
__device__ int   g_deg[N_NODES];
__device__ float g_dinv[N_NODES];
__device__ int   g_rowptr[N_NODES + 1];
__device__ int   g_cursor[N_NODES];
__device__ int2  g_csr[N_EDGES];       // .x = src node, .y = bits of dinv[src]
__device__ int   g_partial[256];
__device__ float g_ssum[N_GRAPHS * HD];
__device__ float g_cnt[N_GRAPHS];

// ---------------- setup 0: deg=1 + zero pool ---------------------------------
__global__ void k_init() {
    int i = blockIdx.x * blockDim.x + threadIdx.x;
    if (i < N_NODES) g_deg[i] = 1;           // self loop
    if (i < N_GRAPHS * HD) g_ssum[i] = 0.f;
    if (i < N_GRAPHS)      g_cnt[i] = 0.f;
}

// ---------------- setup 1: degree count --------------------------------------
__global__ void k_count(const int* __restrict__ dst) {
    int e = blockIdx.x * blockDim.x + threadIdx.x;
    if (e < N_EDGES) atomicAdd(&g_deg[dst[e]], 1);
}

// ---------------- setup 2: block totals of (deg-1) + dinv --------------------
__global__ void k_scan_a() {
    __shared__ int sh[512];
    int tid = threadIdx.x;
    int i = blockIdx.x * 512 + tid;
    int d = (i < N_NODES) ? g_deg[i] : 1;
    if (i < N_NODES) g_dinv[i] = rsqrtf((float)d);
    sh[tid] = d - 1;
    __syncthreads();
    for (int off = 256; off > 0; off >>= 1) {
        if (tid < off) sh[tid] += sh[tid + off];
        __syncthreads();
    }
    if (tid == 0) g_partial[blockIdx.x] = sh[0];
}

// ---------------- setup 3: full scan (block offset computed inline) ----------
__global__ void k_scan_c() {
    __shared__ int sh[512];
    __shared__ int shp[512];
    int tid = threadIdx.x;
    int i = blockIdx.x * 512 + tid;

    // block offset = sum of g_partial[0 .. blockIdx.x)
    shp[tid] = (tid < blockIdx.x) ? g_partial[tid] : 0;   // blockIdx.x <= 195 < 256
    __syncthreads();
    for (int off = 256; off > 0; off >>= 1) {
        if (tid < off) shp[tid] += shp[tid + off];
        __syncthreads();
    }
    int offset = shp[0];

    int v = (i < N_NODES) ? (g_deg[i] - 1) : 0;
    sh[tid] = v;
    __syncthreads();
    for (int off = 1; off < 512; off <<= 1) {
        int t = (tid >= off) ? sh[tid - off] : 0;
        __syncthreads();
        sh[tid] += t;
        __syncthreads();
    }
    if (i < N_NODES) {
        int ex = offset + sh[tid] - v;
        g_rowptr[i] = ex;
        g_cursor[i] = ex;
    }
    if (blockIdx.x == 0 && tid == 0) g_rowptr[N_NODES] = N_EDGES;
}

// ---------------- setup 4: scatter edges into CSR ----------------------------
__global__ void k_scatter(const int* __restrict__ src, const int* __restrict__ dst) {
    int e = blockIdx.x * blockDim.x + threadIdx.x;
    if (e >= N_EDGES) return;
    int d = dst[e];
    int s = src[e];
    int p = atomicAdd(&g_cursor[d], 1);
    g_csr[p] = make_int2(s, __float_as_int(g_dinv[s]));
}

// ---------------- GEMM: Yh = half(X @ W) via packed fma.rn.f32x2 -------------
__global__ void __launch_bounds__(256) k_gemm(const float* __restrict__ Xext, int xsel,
                                              const float* __restrict__ W) {
    __shared__ float xs[64 * 128];
    const float* X = (xsel < 0) ? Xext : (xsel == 0 ? (const float*)g_xa : (const float*)g_xb);

    int tid  = threadIdx.x;
    int c    = tid & 63;
    int rsub = tid >> 6;

    float w[64];
#pragma unroll
    for (int k = 0; k < 64; k++) w[k] = W[k * 64 + c];

    int rt = blockIdx.x * 128;
#pragma unroll
    for (int it = 0; it < 8; it++) {
        int idx = it * 256 + tid;
        int cq  = idx & 15;
        int row = idx >> 4;
        int grow = rt + row;
        float4 x4 = make_float4(0.f, 0.f, 0.f, 0.f);
        if (grow < N_NODES) x4 = *(const float4*)&X[grow * 64 + 4 * cq];
        int u  = row >> 1;
        int rb = row & 1;
        float vals[4] = {x4.x, x4.y, x4.z, x4.w};
#pragma unroll
        for (int m = 0; m < 4; m++) {
            int K  = 4 * cq + m;
            int gk = (K + (K >> 2)) & 15;
            xs[K * 128 + 2 * (u ^ gk) + rb] = vals[m];
        }
    }
    __syncthreads();

    unsigned long long acc[16];
#pragma unroll
    for (int j = 0; j < 16; j++) acc[j] = 0ULL;

#pragma unroll
    for (int k = 0; k < 64; k++) {
        const int g = (k + (k >> 2)) & 15;
        unsigned long long wp;
        asm("mov.b64 %0, {%1, %1};" : "=l"(wp) : "f"(w[k]));
        const float* base = &xs[k * 128 + rsub * 32];
#pragma unroll
        for (int j = 0; j < 16; j++) {
            float2 x2 = *(const float2*)&base[2 * (j ^ g)];
            unsigned long long xv;
            asm("mov.b64 %0, {%1, %2};" : "=l"(xv) : "f"(x2.x), "f"(x2.y));
            asm("fma.rn.f32x2 %0, %1, %2, %0;" : "+l"(acc[j]) : "l"(xv), "l"(wp));
        }
    }

#pragma unroll
    for (int j = 0; j < 16; j++) {
        int row = rt + rsub * 32 + 2 * j;
        float lo, hi;
        asm("mov.b64 {%0, %1}, %2;" : "=f"(lo), "=f"(hi) : "l"(acc[j]));
        if (row < N_NODES)     g_yh[row * 64 + c]       = __float2half_rn(lo);
        if (row + 1 < N_NODES) g_yh[(row + 1) * 64 + c] = __float2half_rn(hi);
    }
}

// ---------------- fused aggregation + bias + ReLU + BN + residual ------------
// 2 nodes per warp (one per half-warp); lane handles 4 dims (uint2 = 4 halves).
// fp16 rows: one 128B line per edge. Unroll-4 for MLP.
__device__ __forceinline__ float4 h4_to_f4(uint2 u) {
    float2 lo = __half22float2(*(__half2*)&u.x);
    float2 hi = __half22float2(*(__half2*)&u.y);
    return make_float4(lo.x, lo.y, hi.x, hi.y);
}

__global__ void __launch_bounds__(256) k_agg(int res_sel, int out_sel,
                                             const float* __restrict__ bias,
                                             const float* __restrict__ gamma,
                                             const float* __restrict__ beta,
                                             const float* __restrict__ mean,
                                             const float* __restrict__ var) {
    int gw   = (blockIdx.x * blockDim.x + threadIdx.x) >> 5;
    int lane = threadIdx.x & 31;
    int node = gw * 2 + (lane >> 4);
    if (node >= N_NODES) return;
    int q = lane & 15;

    const __half* Yh  = g_yh;
    float*        OUT = out_sel ? g_xb : g_xa;
    const float*  RES = (res_sel < 0) ? nullptr
                                      : (res_sel == 0 ? (const float*)g_xa : (const float*)g_xb);

    int beg = g_rowptr[node], end = g_rowptr[node + 1];
    float4 a = make_float4(0.f, 0.f, 0.f, 0.f);

    int e = beg;
    for (; e + 3 < end; e += 4) {
        int2 c0 = g_csr[e];
        int2 c1 = g_csr[e + 1];
        int2 c2 = g_csr[e + 2];
        int2 c3 = g_csr[e + 3];
        uint2 u0 = ((const uint2*)(Yh + (size_t)c0.x * 64))[q];
        uint2 u1 = ((const uint2*)(Yh + (size_t)c1.x * 64))[q];
        uint2 u2 = ((const uint2*)(Yh + (size_t)c2.x * 64))[q];
        uint2 u3 = ((const uint2*)(Yh + (size_t)c3.x * 64))[q];
        float4 v0 = h4_to_f4(u0), v1 = h4_to_f4(u1);
        float4 v2 = h4_to_f4(u2), v3 = h4_to_f4(u3);
        float w0 = __int_as_float(c0.y), w1 = __int_as_float(c1.y);
        float w2 = __int_as_float(c2.y), w3 = __int_as_float(c3.y);
        a.x += w0 * v0.x + w1 * v1.x + w2 * v2.x + w3 * v3.x;
        a.y += w0 * v0.y + w1 * v1.y + w2 * v2.y + w3 * v3.y;
        a.z += w0 * v0.z + w1 * v1.z + w2 * v2.z + w3 * v3.z;
        a.w += w0 * v0.w + w1 * v1.w + w2 * v2.w + w3 * v3.w;
    }
    for (; e < end; e++) {
        int2 c0 = g_csr[e];
        uint2 u0 = ((const uint2*)(Yh + (size_t)c0.x * 64))[q];
        float4 v0 = h4_to_f4(u0);
        float w0 = __int_as_float(c0.y);
        a.x += w0 * v0.x;  a.y += w0 * v0.y;
        a.z += w0 * v0.z;  a.w += w0 * v0.w;
    }

    float  di = g_dinv[node];
    float4 self = h4_to_f4(((const uint2*)(Yh + (size_t)node * 64))[q]);
    float4 b  = ((const float4*)bias)[q];
    a.x = di * (a.x + di * self.x) + b.x;
    a.y = di * (a.y + di * self.y) + b.y;
    a.z = di * (a.z + di * self.z) + b.z;
    a.w = di * (a.w + di * self.w) + b.w;
    a.x = fmaxf(a.x, 0.f); a.y = fmaxf(a.y, 0.f);
    a.z = fmaxf(a.z, 0.f); a.w = fmaxf(a.w, 0.f);

    float4 ga = ((const float4*)gamma)[q];
    float4 be = ((const float4*)beta)[q];
    float4 mm = ((const float4*)mean)[q];
    float4 vv = ((const float4*)var)[q];
    float4 sc;
    sc.x = ga.x * rsqrtf(vv.x + EPSV);
    sc.y = ga.y * rsqrtf(vv.y + EPSV);
    sc.z = ga.z * rsqrtf(vv.z + EPSV);
    sc.w = ga.w * rsqrtf(vv.w + EPSV);
    a.x = (a.x - mm.x) * sc.x + be.x;
    a.y = (a.y - mm.y) * sc.y + be.y;
    a.z = (a.z - mm.z) * sc.z + be.z;
    a.w = (a.w - mm.w) * sc.w + be.w;

    if (RES) {
        float4 r = ((const float4*)(RES + (size_t)node * 64))[q];
        a.x += r.x; a.y += r.y; a.z += r.z; a.w += r.w;
    }
    ((float4*)(OUT + (size_t)node * 64))[q] = a;
}

// ---------------- pooling (batch sorted -> run-length accumulate) ------------
__global__ void k_pool(const int* __restrict__ batch) {
    const float* X5 = (const float*)g_xa;
    int c = threadIdx.x;
    int start = blockIdx.x * 512;
    if (start >= N_NODES) return;
    int endn = min(start + 512, N_NODES);
    float acc = 0.f;
    int run = 0;
    int gcur = batch[start];
    for (int n = start; n < endn; n++) {
        int g = batch[n];
        if (g != gcur) {
            atomicAdd(&g_ssum[gcur * 64 + c], acc);
            if (c == 0) atomicAdd(&g_cnt[gcur], (float)run);
            acc = 0.f; run = 0; gcur = g;
        }
        acc += X5[n * 64 + c];
        run++;
    }
    atomicAdd(&g_ssum[gcur * 64 + c], acc);
    if (c == 0) atomicAdd(&g_cnt[gcur], (float)run);
}

// ---------------- MLP head ---------------------------------------------------
__global__ void k_head(const float* __restrict__ hW1, const float* __restrict__ hb1,
                       const float* __restrict__ hg,  const float* __restrict__ hbeta,
                       const float* __restrict__ hm,  const float* __restrict__ hv,
                       const float* __restrict__ hW2, const float* __restrict__ hb2,
                       float* __restrict__ out) {
    int g = threadIdx.x;
    if (g >= N_GRAPHS) return;
    float inv = 1.f / fmaxf(g_cnt[g], 1.f);
    float gv[64];
#pragma unroll
    for (int k = 0; k < 64; k++) gv[k] = g_ssum[g * 64 + k] * inv;
    float o = hb2[0];
    for (int j = 0; j < 32; j++) {
        float s = hb1[j];
#pragma unroll
        for (int k = 0; k < 64; k++) s += gv[k] * hW1[k * 32 + j];
        s = fmaxf(s, 0.f);
        s = (s - hm[j]) * (hg[j] * rsqrtf(hv[j] + EPSV)) + hbeta[j];
        o += s * hW2[j];
    }
    out[g] = o;
}

// ---------------- launcher ---------------------------------------------------
extern "C" void kernel_launch(void* const* d_in, const int* in_sizes, int n_in,
                              void* d_out, int out_size) {
    const float* x     = (const float*)d_in[0];
    const int*   ei    = (const int*)  d_in[1];
    const int*   batch = (const int*)  d_in[2];
    const float* Wc    = (const float*)d_in[3];
    const float* bc    = (const float*)d_in[4];
    const float* bn_g  = (const float*)d_in[5];
    const float* bn_b  = (const float*)d_in[6];
    const float* bn_m  = (const float*)d_in[7];
    const float* bn_v  = (const float*)d_in[8];
    const float* hW1   = (const float*)d_in[9];
    const float* hb1   = (const float*)d_in[10];
    const float* hg    = (const float*)d_in[11];
    const float* hbe   = (const float*)d_in[12];
    const float* hm    = (const float*)d_in[13];
    const float* hv    = (const float*)d_in[14];
    const float* hW2   = (const float*)d_in[15];
    const float* hb2   = (const float*)d_in[16];
    float* out = (float*)d_out;

    const int* src = ei;
    const int* dst = ei + N_EDGES;

    // --- CSR build: 5 launches (so first gemm is launch #5 for ncu capture) ---
    k_init   <<<(N_NODES + 255) / 256, 256>>>();
    k_count  <<<(N_EDGES + 255) / 256, 256>>>(dst);
    int nblk = (N_NODES + 511) / 512;       // 196
    k_scan_a <<<nblk, 512>>>();
    k_scan_c <<<nblk, 512>>>();
    k_scatter<<<(N_EDGES + 255) / 256, 256>>>(src, dst);

    // --- 5 GCN layers ---
    const int gemm_grid = (N_NODES + 127) / 128;
    const int agg_grid  = ((N_NODES + 1) / 2 * 32 + 255) / 256;

    k_gemm<<<gemm_grid, 256>>>(x, -1, Wc + 0 * 4096);
    k_agg <<<agg_grid, 256>>>(-1, 0, bc + 0, bn_g + 0, bn_b + 0, bn_m + 0, bn_v + 0);
    k_gemm<<<gemm_grid, 256>>>(nullptr, 0, Wc + 1 * 4096);
    k_agg <<<agg_grid, 256>>>(0, 1, bc + 64, bn_g + 64, bn_b + 64, bn_m + 64, bn_v + 64);
    k_gemm<<<gemm_grid, 256>>>(nullptr, 1, Wc + 2 * 4096);
    k_agg <<<agg_grid, 256>>>(1, 0, bc + 128, bn_g + 128, bn_b + 128, bn_m + 128, bn_v + 128);
    k_gemm<<<gemm_grid, 256>>>(nullptr, 0, Wc + 3 * 4096);
    k_agg <<<agg_grid, 256>>>(0, 1, bc + 192, bn_g + 192, bn_b + 192, bn_m + 192, bn_v + 192);
    k_gemm<<<gemm_grid, 256>>>(nullptr, 1, Wc + 4 * 4096);
    k_agg <<<agg_grid, 256>>>(1, 0, bc + 256, bn_g + 256, bn_b + 256, bn_m + 256, bn_v + 256);

    // --- pool + head ---
    k_pool<<<(N_NODES + 511) / 512, 64>>>(batch);
    k_head<<<1, 64>>>(hW1, hb1, hg, hbe, hm, hv, hW2, hb2, out);
}